// round 10
// baseline (speedup 1.0000x reference)
#include <cuda_runtime.h>

// ---- problem constants ----
#define Gg      180
#define NATOMS  64
#define NRAD    8
#define NANG    16
#define NACC    128
#define RMAXI   13
#define BDIM    27
#define NROWS   (BDIM*BDIM)        // 729 (i,j) rows of 27 k-cells
#define NSPLIT  6
#define NTH     128
#define NWARP   (NTH/32)
#define CAPW    512                // per-warp compacted-list capacity (u16)
#define SHIFT_C 1.25f

#define A_F   (0.2f)
#define RO_F  (2.5f)

// scratch (static __device__: no allocation)
__device__ float g_part[NATOMS * NSPLIT * NWARP * NACC];
__device__ int   g_cnt[NATOMS];          // self-resetting arrival counters

__global__ __launch_bounds__(NTH, 3)
void proj_kernel(const float* __restrict__ rho, const float* __restrict__ pos,
                 const float* __restrict__ W, float* __restrict__ out)
{
    const int split = blockIdx.x;
    const int atom  = blockIdx.y;
    const int tid   = threadIdx.x;
    const int warp  = tid >> 5;
    const int lane  = tid & 31;

    __shared__ float sOfs[3][BDIM];
    __shared__ int   sIdx[3][BDIM];
    __shared__ unsigned short slist[NWARP * CAPW];
    __shared__ int   scnt[NWARP];
    __shared__ int   s_old;
    __shared__ float sred[NTH][33];      // chunked transpose for reduction

    // ---------- per-dimension stencil setup ----------
    if (tid < 3 * BDIM) {
        int dim = tid / BDIM;
        int o   = tid - dim * BDIM;
        int off = o - RMAXI;
        float p  = pos[atom * 3 + dim];
        float cm = rintf(p / A_F);                 // round-half-even == jnp.round
        float dr = __fadd_rn(p, -__fmul_rn(A_F, cm));
        int ci = (int)cm + off;
        if (ci < 0)   ci += Gg;
        if (ci >= Gg) ci -= Gg;
        sIdx[dim][o] = ci;
        sOfs[dim][o] = __fadd_rn(__fmul_rn((float)off, A_F), -dr);
    }
    __syncthreads();

    // ---------- phase 1: per-warp compaction, rows round-robin across splits ----------
    const float ro2 = RO_F * RO_F;
    const int nrows = (NROWS - split + NSPLIT - 1) / NSPLIT;   // rows r = split + 6*ri
    const int ntot  = nrows * BDIM;
    const int nit   = (ntot + NTH - 1) / NTH;
    int wbase = 0;
    #pragma unroll 1
    for (int it = 0; it < nit; ++it) {
        int idx = it * NTH + tid;
        bool valid = idx < ntot;
        unsigned ii = valid ? (unsigned)idx : 0u;
        unsigned ri = ii / 27u;
        unsigned kk = ii - ri * 27u;
        unsigned r  = (unsigned)split + ri * NSPLIT;
        unsigned i  = r / 27u;
        unsigned j  = r - i * 27u;
        float x = sOfs[0][i], y = sOfs[1][j], z = sOfs[2][kk];
        float r2 = x * x + y * y + z * z;
        bool pred = valid && (r2 < ro2);
        unsigned mask = __ballot_sync(0xFFFFFFFFu, pred);
        if (pred) {
            int p = wbase + __popc(mask & ((1u << lane) - 1u));
            if (p < CAPW)
                slist[warp * CAPW + p] = (unsigned short)((i << 10) | (j << 5) | kk);
        }
        wbase += __popc(mask);
    }
    if (lane == 0) scnt[warp] = (wbase < CAPW) ? wbase : CAPW;
    __syncthreads();

    // ---------- phase 2: dense accumulation, shifted moment basis ----------
    float acc[NACC];                       // acc[m*16+lm],  nu_m = sum base*s^m
    #pragma unroll
    for (int q = 0; q < NACC; ++q) acc[q] = 0.0f;

    {
        const int cnt = scnt[warp];
        const unsigned short* lst = &slist[warp * CAPW];
        int idx = lane;
        if (idx < cnt) {
            unsigned cell = lst[idx];
            int i0 = cell >> 10, j0 = (cell >> 5) & 31, k0 = cell & 31;
            float rv = __ldg(&rho[(sIdx[0][i0] * Gg + sIdx[1][j0]) * Gg + sIdx[2][k0]]);

            #pragma unroll 1
            while (true) {
                // prefetch next cell + density
                int nidx = idx + 32;
                bool more = nidx < cnt;
                unsigned ncell = 0; float nrv = 0.0f;
                if (more) {
                    ncell = lst[nidx];
                    int ni = ncell >> 10, nj = (ncell >> 5) & 31, nk = ncell & 31;
                    nrv = __ldg(&rho[(sIdx[0][ni] * Gg + sIdx[1][nj]) * Gg + sIdx[2][nk]]);
                }

                int i = cell >> 10, j = (cell >> 5) & 31, k = cell & 31;
                float x = sOfs[0][i], y = sOfs[1][j], z = sOfs[2][k];
                float r2 = x * x + y * y + z * z;
                float rinv = rsqrtf(fmaxf(r2, 1e-24f));
                float R  = r2 * rinv;
                float b  = RO_F - R;
                float s  = b - SHIFT_C;

                // t_m = r2*b^2*rho * s^m
                float t[NRAD];
                t[0] = r2 * (b * b) * rv;
                #pragma unroll
                for (int m = 1; m < NRAD; ++m) t[m] = t[m - 1] * s;

                float ux = x * rinv, uy = y * rinv, uz = z * rinv;
                float ux2 = ux * ux, uy2 = uy * uy, uz2 = uz * uz;

                // fused: per lm compute Y inline then 8 FMAs (keeps regs ~162)
                #define ACCY(lm, expr) { float yv = (expr);                         \
                    _Pragma("unroll")                                               \
                    for (int m = 0; m < NRAD; ++m)                                  \
                        acc[m * NANG + (lm)] = fmaf(t[m], yv, acc[m * NANG + (lm)]); }

                ACCY(0,  0.28209479177387814f)
                ACCY(1,  0.4886025119029199f * uy)
                ACCY(2,  0.4886025119029199f * uz)
                ACCY(3,  0.4886025119029199f * ux)
                ACCY(4,  0.5462742152960396f * (2.0f * ux * uy))
                ACCY(5,  1.0925484305920792f * (uy * uz))
                ACCY(6,  0.31539156525252005f * (3.0f * uz2 - 1.0f))
                ACCY(7,  1.0925484305920792f * (ux * uz))
                ACCY(8,  0.5462742152960396f * (ux2 - uy2))
                ACCY(9,  0.5900435899266435f * uy * (3.0f * ux2 - uy2))
                ACCY(10, 1.445305721320277f  * (2.0f * ux * uy * uz))
                ACCY(11, 0.4570457994644658f * uy * (5.0f * uz2 - 1.0f))
                ACCY(12, 0.3731763325901154f * uz * (5.0f * uz2 - 3.0f))
                ACCY(13, 0.4570457994644658f * ux * (5.0f * uz2 - 1.0f))
                ACCY(14, 1.445305721320277f  * (ux2 - uy2) * uz)
                ACCY(15, 0.5900435899266435f * ux * (ux2 - 3.0f * uy2))
                #undef ACCY

                if (!more) break;
                idx = nidx; cell = ncell; rv = nrv;
            }
        }
    }

    // ---------- block reduction: 4 chunks of 32 coeffs via shared transpose ----------
    // per-warp (seg) partials are written; finalize sums NSPLIT*NWARP partials
    #pragma unroll 1
    for (int ch = 0; ch < 4; ++ch) {
        #pragma unroll
        for (int c = 0; c < 32; ++c) sred[tid][c] = acc[ch * 32 + c];
        __syncthreads();
        {
            int q   = tid & 31;
            int seg = tid >> 5;
            float v = 0.0f;
            #pragma unroll
            for (int t = 0; t < 32; ++t) v += sred[seg * 32 + t][q];
            g_part[(((atom * NSPLIT + split) * NWARP) + seg) * NACC + ch * 32 + q] = v;
        }
        __syncthreads();
    }

    // ---------- last-block-per-atom finalization (fp64, W * binomial-shift) ----------
    __threadfence();
    if (tid == 0) s_old = atomicAdd(&g_cnt[atom], 1);
    __syncthreads();
    if (s_old == NSPLIT - 1) {
        __threadfence();
        const int lm = tid & 15;
        const int n  = tid >> 4;

        // nu_k[lm] summed over all split/warp partials, in double
        double vk[NRAD];
        #pragma unroll
        for (int k = 0; k < NRAD; ++k) {
            double a = 0.0;
            for (int pp = 0; pp < NSPLIT * NWARP; ++pp)
                a += (double)g_part[(atom * NSPLIT * NWARP + pp) * NACC + k * NANG + lm];
            vk[k] = a;
        }

        // mu_m = sum_k binom(m,k) c^{m-k} nu_k ; coeff_n = sum_m W[n,m] mu_m
        const double binom[NRAD][NRAD] = {
            {1,0,0,0,0,0,0,0},{1,1,0,0,0,0,0,0},{1,2,1,0,0,0,0,0},{1,3,3,1,0,0,0,0},
            {1,4,6,4,1,0,0,0},{1,5,10,10,5,1,0,0},{1,6,15,20,15,6,1,0},{1,7,21,35,35,21,7,1}};
        double cp[NRAD];
        cp[0] = 1.0;
        #pragma unroll
        for (int k = 1; k < NRAD; ++k) cp[k] = cp[k - 1] * (double)SHIFT_C;

        double mu[NRAD];
        #pragma unroll
        for (int m = 0; m < NRAD; ++m) {
            double a = 0.0;
            #pragma unroll
            for (int k = 0; k <= m; ++k) a += binom[m][k] * cp[m - k] * vk[k];
            mu[m] = a;
        }

        const double vcell = (36.0 / 180.0) * (36.0 / 180.0) * (36.0 / 180.0);
        double sacc = 0.0;
        #pragma unroll
        for (int m = 0; m < NRAD; ++m)
            sacc += (double)W[n * NRAD + m] * mu[m];
        out[atom * NACC + n * NANG + lm] = (float)(sacc * vcell);

        if (tid == 0) g_cnt[atom] = 0;       // reset for graph replay
    }
}

extern "C" void kernel_launch(void* const* d_in, const int* in_sizes, int n_in,
                              void* d_out, int out_size)
{
    const float* rho = (const float*)d_in[0];   // [180,180,180]
    const float* pos = (const float*)d_in[1];   // [64,3]
    const float* W   = (const float*)d_in[2];   // [8,8]
    float* out = (float*)d_out;                 // [64,128]

    dim3 grid(NSPLIT, NATOMS);                  // 6 x 64 = 384 blocks
    proj_kernel<<<grid, NTH>>>(rho, pos, W, out);
}

// round 11
// speedup vs baseline: 1.5235x; 1.5235x over previous
#include <cuda_runtime.h>

// ---- problem constants ----
#define Gg      180
#define NATOMS  64
#define NRAD    8
#define NANG    16
#define NACC    128
#define RMAXI   13
#define BDIM    27
#define NROWS   (BDIM*BDIM)        // 729 (i,j) rows of 27 k-cells
#define NSPLIT  4
#define NTH     128
#define NWARP   (NTH/32)
#define NSW     (NSPLIT*NWARP)     // 16 row classes
#define CAPW    704                // per-warp compacted-list capacity (8B entries)
#define SHIFT_C 1.25f

#define A_F   (0.2f)
#define RO_F  (2.5f)

// scratch (static __device__: no allocation)
__device__ float g_part[NATOMS * NSPLIT * NWARP * NACC];
__device__ int   g_cnt[NATOMS];          // self-resetting arrival counters

__global__ __launch_bounds__(NTH)
void proj_kernel(const float* __restrict__ rho, const float* __restrict__ pos,
                 const float* __restrict__ W, float* __restrict__ out)
{
    const int split = blockIdx.x;
    const int atom  = blockIdx.y;
    const int tid   = threadIdx.x;
    const int warp  = tid >> 5;
    const int lane  = tid & 31;

    __shared__ float sOfs[3][BDIM];
    __shared__ int   sIdx[3][BDIM];
    __shared__ unsigned long long slist[NWARP * CAPW];  // low32: rho offset, [32:47): ijk
    __shared__ int   scnt[NWARP];
    __shared__ int   s_old;
    __shared__ float sred[NTH][33];      // chunked transpose for reduction

    // ---------- per-dimension stencil setup ----------
    if (tid < 3 * BDIM) {
        int dim = tid / BDIM;
        int o   = tid - dim * BDIM;
        int off = o - RMAXI;
        float p  = pos[atom * 3 + dim];
        float cm = rintf(p / A_F);                 // round-half-even == jnp.round
        float dr = __fadd_rn(p, -__fmul_rn(A_F, cm));
        int ci = (int)cm + off;
        if (ci < 0)   ci += Gg;
        if (ci >= Gg) ci -= Gg;
        sIdx[dim][o] = ci;
        sOfs[dim][o] = __fadd_rn(__fmul_rn((float)off, A_F), -dr);
    }
    // per-thread dr for coordinate reconstruction in phase 2
    float drx, dry, drz;
    {
        float px = pos[atom * 3 + 0], py = pos[atom * 3 + 1], pz = pos[atom * 3 + 2];
        drx = __fadd_rn(px, -__fmul_rn(A_F, rintf(px / A_F)));
        dry = __fadd_rn(py, -__fmul_rn(A_F, rintf(py / A_F)));
        drz = __fadd_rn(pz, -__fmul_rn(A_F, rintf(pz / A_F)));
    }
    __syncthreads();

    // ---------- phase 1: warp-autonomous compaction, rows round-robin over 16 classes ----------
    const float ro2 = RO_F * RO_F;
    const int sw = split * NWARP + warp;                 // 0..15: this warp's row class
    const int nrows_w = (NROWS - sw + NSW - 1) / NSW;    // rows r = sw + 16*ri
    const int ntot = nrows_w * BDIM;
    const int nit  = (ntot + 31) / 32;
    int wbase = 0;
    #pragma unroll 1
    for (int it = 0; it < nit; ++it) {
        int idx = it * 32 + lane;
        bool valid = idx < ntot;
        unsigned ii = valid ? (unsigned)idx : 0u;
        unsigned ri = ii / 27u;
        unsigned kk = ii - ri * 27u;
        unsigned r  = (unsigned)sw + ri * NSW;
        unsigned i  = r / 27u;
        unsigned j  = r - i * 27u;
        float x = sOfs[0][i], y = sOfs[1][j], z = sOfs[2][kk];
        float r2 = x * x + y * y + z * z;
        bool pred = valid && (r2 < ro2);
        unsigned mask = __ballot_sync(0xFFFFFFFFu, pred);
        if (pred) {
            int p = wbase + __popc(mask & ((1u << lane) - 1u));
            if (p < CAPW) {
                unsigned off = (unsigned)((sIdx[0][i] * Gg + sIdx[1][j]) * Gg + sIdx[2][kk]);
                unsigned pk  = (i << 10) | (j << 5) | kk;
                slist[warp * CAPW + p] = (unsigned long long)off
                                       | ((unsigned long long)pk << 32);
            }
        }
        wbase += __popc(mask);
    }
    if (lane == 0) scnt[warp] = (wbase < CAPW) ? wbase : CAPW;
    __syncwarp();

    // ---------- phase 2: dense accumulation, shifted moment basis, LDS-gather-free ----------
    float acc[NACC];                       // acc[m*16+lm],  nu_m = sum base*s^m
    #pragma unroll
    for (int q = 0; q < NACC; ++q) acc[q] = 0.0f;

    {
        const int cnt = scnt[warp];
        const unsigned long long* lst = &slist[warp * CAPW];
        int idx = lane;
        if (idx < cnt) {
            unsigned long long e = lst[idx];
            float rv = __ldg(&rho[(unsigned)e]);

            #pragma unroll 1
            while (true) {
                // prefetch next entry + density
                int nidx = idx + 32;
                bool more = nidx < cnt;
                unsigned long long ne = 0; float nrv = 0.0f;
                if (more) {
                    ne = lst[nidx];
                    nrv = __ldg(&rho[(unsigned)ne]);
                }

                unsigned pk = (unsigned)(e >> 32);
                int i = (int)(pk >> 10), j = (int)((pk >> 5) & 31), k = (int)(pk & 31);
                // reconstruct coordinates: x = (i-13)*0.2f - drx  (same rounding as setup)
                float x = __fadd_rn(__fmul_rn((float)(i - RMAXI), A_F), -drx);
                float y = __fadd_rn(__fmul_rn((float)(j - RMAXI), A_F), -dry);
                float z = __fadd_rn(__fmul_rn((float)(k - RMAXI), A_F), -drz);

                float r2 = x * x + y * y + z * z;
                float rinv = rsqrtf(fmaxf(r2, 1e-24f));
                float R  = r2 * rinv;
                float b  = RO_F - R;
                float s  = b - SHIFT_C;

                // t_m = r2*b^2*rho * s^m
                float t[NRAD];
                t[0] = r2 * (b * b) * rv;
                #pragma unroll
                for (int m = 1; m < NRAD; ++m) t[m] = t[m - 1] * s;

                float ux = x * rinv, uy = y * rinv, uz = z * rinv;
                float ux2 = ux * ux, uy2 = uy * uy, uz2 = uz * uz;

                #define ACCY(lm, expr) { float yv = (expr);                         \
                    _Pragma("unroll")                                               \
                    for (int m = 0; m < NRAD; ++m)                                  \
                        acc[m * NANG + (lm)] = fmaf(t[m], yv, acc[m * NANG + (lm)]); }

                ACCY(0,  0.28209479177387814f)
                ACCY(1,  0.4886025119029199f * uy)
                ACCY(2,  0.4886025119029199f * uz)
                ACCY(3,  0.4886025119029199f * ux)
                ACCY(4,  0.5462742152960396f * (2.0f * ux * uy))
                ACCY(5,  1.0925484305920792f * (uy * uz))
                ACCY(6,  0.31539156525252005f * (3.0f * uz2 - 1.0f))
                ACCY(7,  1.0925484305920792f * (ux * uz))
                ACCY(8,  0.5462742152960396f * (ux2 - uy2))
                ACCY(9,  0.5900435899266435f * uy * (3.0f * ux2 - uy2))
                ACCY(10, 1.445305721320277f  * (2.0f * ux * uy * uz))
                ACCY(11, 0.4570457994644658f * uy * (5.0f * uz2 - 1.0f))
                ACCY(12, 0.3731763325901154f * uz * (5.0f * uz2 - 3.0f))
                ACCY(13, 0.4570457994644658f * ux * (5.0f * uz2 - 1.0f))
                ACCY(14, 1.445305721320277f  * (ux2 - uy2) * uz)
                ACCY(15, 0.5900435899266435f * ux * (ux2 - 3.0f * uy2))
                #undef ACCY

                if (!more) break;
                idx = nidx; e = ne; rv = nrv;
            }
        }
    }

    // ---------- block reduction: 4 chunks of 32 coeffs via shared transpose ----------
    __syncthreads();    // slist reads done before sred overlaps (separate arrays; ordering only)
    #pragma unroll 1
    for (int ch = 0; ch < 4; ++ch) {
        #pragma unroll
        for (int c = 0; c < 32; ++c) sred[tid][c] = acc[ch * 32 + c];
        __syncthreads();
        {
            int q   = tid & 31;
            int seg = tid >> 5;
            float v = 0.0f;
            #pragma unroll
            for (int t = 0; t < 32; ++t) v += sred[seg * 32 + t][q];
            g_part[(((atom * NSPLIT + split) * NWARP) + seg) * NACC + ch * 32 + q] = v;
        }
        __syncthreads();
    }

    // ---------- last-block-per-atom finalization (fp64, W * binomial-shift) ----------
    __threadfence();
    if (tid == 0) s_old = atomicAdd(&g_cnt[atom], 1);
    __syncthreads();
    if (s_old == NSPLIT - 1) {
        __threadfence();
        const int lm = tid & 15;
        const int n  = tid >> 4;

        double vk[NRAD];
        #pragma unroll
        for (int k = 0; k < NRAD; ++k) {
            double a = 0.0;
            for (int pp = 0; pp < NSPLIT * NWARP; ++pp)
                a += (double)g_part[(atom * NSPLIT * NWARP + pp) * NACC + k * NANG + lm];
            vk[k] = a;
        }

        const double binom[NRAD][NRAD] = {
            {1,0,0,0,0,0,0,0},{1,1,0,0,0,0,0,0},{1,2,1,0,0,0,0,0},{1,3,3,1,0,0,0,0},
            {1,4,6,4,1,0,0,0},{1,5,10,10,5,1,0,0},{1,6,15,20,15,6,1,0},{1,7,21,35,35,21,7,1}};
        double cp[NRAD];
        cp[0] = 1.0;
        #pragma unroll
        for (int k = 1; k < NRAD; ++k) cp[k] = cp[k - 1] * (double)SHIFT_C;

        double mu[NRAD];
        #pragma unroll
        for (int m = 0; m < NRAD; ++m) {
            double a = 0.0;
            #pragma unroll
            for (int k = 0; k <= m; ++k) a += binom[m][k] * cp[m - k] * vk[k];
            mu[m] = a;
        }

        const double vcell = (36.0 / 180.0) * (36.0 / 180.0) * (36.0 / 180.0);
        double sacc = 0.0;
        #pragma unroll
        for (int m = 0; m < NRAD; ++m)
            sacc += (double)W[n * NRAD + m] * mu[m];
        out[atom * NACC + n * NANG + lm] = (float)(sacc * vcell);

        if (tid == 0) g_cnt[atom] = 0;       // reset for graph replay
    }
}

extern "C" void kernel_launch(void* const* d_in, const int* in_sizes, int n_in,
                              void* d_out, int out_size)
{
    const float* rho = (const float*)d_in[0];   // [180,180,180]
    const float* pos = (const float*)d_in[1];   // [64,3]
    const float* W   = (const float*)d_in[2];   // [8,8]
    float* out = (float*)d_out;                 // [64,128]

    dim3 grid(NSPLIT, NATOMS);                  // 4 x 64 = 256 blocks
    proj_kernel<<<grid, NTH>>>(rho, pos, W, out);
}

// round 13
// speedup vs baseline: 1.5257x; 1.0014x over previous
#include <cuda_runtime.h>

// ---- problem constants ----
#define Gg      180
#define NATOMS  64
#define NRAD    8
#define NANG    16
#define NACC    128
#define NPAIR   64                 // f32x2 accumulators
#define RMAXI   13
#define BDIM    27
#define NROWS   (BDIM*BDIM)        // 729 (i,j) rows of 27 k-cells
#define NSPLIT  4
#define NTH     128
#define NWARP   (NTH/32)
#define NSW     (NSPLIT*NWARP)     // 16 balanced row classes
#define CAPW    704                // per-warp list capacity (8B entries)
#define SHIFT_C 1.25f

#define A_F   (0.2f)
#define RO_F  (2.5f)

// scratch (static __device__: no allocation)
__device__ float g_part[NATOMS * NSPLIT * NWARP * NACC];
__device__ int   g_cnt[NATOMS];          // self-resetting arrival counters

// ---- packed f32x2 helpers (sm_103a) ----
__device__ __forceinline__ unsigned long long pack2(float a, float b) {
    unsigned long long r;
    asm("mov.b64 %0, {%1, %2};" : "=l"(r) : "f"(a), "f"(b));
    return r;
}
__device__ __forceinline__ void ffma2(unsigned long long& acc, unsigned long long a, unsigned long long b) {
    asm("fma.rn.f32x2 %0, %1, %2, %0;" : "+l"(acc) : "l"(a), "l"(b));
}
__device__ __forceinline__ unsigned long long mul2(unsigned long long a, unsigned long long b) {
    unsigned long long r;
    asm("mul.rn.f32x2 %0, %1, %2;" : "=l"(r) : "l"(a), "l"(b));
    return r;
}
__device__ __forceinline__ void unpack2(unsigned long long v, float& a, float& b) {
    asm("mov.b64 {%0, %1}, %2;" : "=f"(a), "=f"(b) : "l"(v));
}

__global__ __launch_bounds__(NTH, 2)     // reg cap 255 -> no spills (proven shape)
void proj_kernel(const float* __restrict__ rho, const float* __restrict__ pos,
                 const float* __restrict__ W, float* __restrict__ out)
{
    const int split = blockIdx.x;
    const int atom  = blockIdx.y;
    const int tid   = threadIdx.x;
    const int warp  = tid >> 5;
    const int lane  = tid & 31;

    __shared__ float sOfs[3][BDIM];
    __shared__ int   sIdx[3][BDIM];
    __shared__ unsigned long long slist[NWARP * CAPW];  // low32: rho offset; [32:47): packed ijk
    __shared__ int   scnt[NWARP];
    __shared__ int   s_old;
    __shared__ float sred[NTH][33];

    // ---------- per-dimension stencil setup ----------
    if (tid < 3 * BDIM) {
        int dim = tid / BDIM;
        int o   = tid - dim * BDIM;
        int off = o - RMAXI;
        float p  = pos[atom * 3 + dim];
        float cm = rintf(p / A_F);                 // round-half-even == jnp.round
        float dr = __fadd_rn(p, -__fmul_rn(A_F, cm));
        int ci = (int)cm + off;
        if (ci < 0)   ci += Gg;
        if (ci >= Gg) ci -= Gg;
        sIdx[dim][o] = ci;
        sOfs[dim][o] = __fadd_rn(__fmul_rn((float)off, A_F), -dr);
    }
    // per-thread dr for coordinate reconstruction in phase 2
    float drx, dry, drz;
    {
        float px = pos[atom * 3 + 0], py = pos[atom * 3 + 1], pz = pos[atom * 3 + 2];
        drx = __fadd_rn(px, -__fmul_rn(A_F, rintf(px / A_F)));
        dry = __fadd_rn(py, -__fmul_rn(A_F, rintf(py / A_F)));
        drz = __fadd_rn(pz, -__fmul_rn(A_F, rintf(pz / A_F)));
    }
    __syncthreads();

    // ---------- phase 1: warp-autonomous compaction, rows round-robin over 16 classes ----------
    const float ro2 = RO_F * RO_F;
    const int sw = split * NWARP + warp;                 // this warp's row class
    const int nrows_w = (NROWS - sw + NSW - 1) / NSW;    // rows r = sw + 16*ri
    const int ntot = nrows_w * BDIM;
    const int nit  = (ntot + 31) / 32;
    int wbase = 0;
    #pragma unroll 1
    for (int it = 0; it < nit; ++it) {
        int idx = it * 32 + lane;
        bool valid = idx < ntot;
        unsigned ii = valid ? (unsigned)idx : 0u;
        unsigned ri = ii / 27u;
        unsigned kk = ii - ri * 27u;
        unsigned r  = (unsigned)sw + ri * NSW;
        unsigned i  = r / 27u;
        unsigned j  = r - i * 27u;
        float x = sOfs[0][i], y = sOfs[1][j], z = sOfs[2][kk];
        float r2 = x * x + y * y + z * z;
        bool pred = valid && (r2 < ro2);
        unsigned mask = __ballot_sync(0xFFFFFFFFu, pred);
        if (pred) {
            int p = wbase + __popc(mask & ((1u << lane) - 1u));
            if (p < CAPW) {
                unsigned off = (unsigned)((sIdx[0][i] * Gg + sIdx[1][j]) * Gg + sIdx[2][kk]);
                unsigned pk  = (i << 10) | (j << 5) | kk;
                slist[warp * CAPW + p] = (unsigned long long)off
                                       | ((unsigned long long)pk << 32);
            }
        }
        wbase += __popc(mask);
    }
    if (lane == 0) scnt[warp] = (wbase < CAPW) ? wbase : CAPW;
    __syncwarp();

    // ---------- phase 2: depth-2 prefetch pipeline, f32x2 accumulation ----------
    unsigned long long acc2[NPAIR];        // acc2[m*8+p] packs coeffs (m, 2p) and (m, 2p+1)
    #pragma unroll
    for (int q = 0; q < NPAIR; ++q) acc2[q] = 0ull;

    {
        const int cnt = scnt[warp];
        const unsigned long long* lst = &slist[warp * CAPW];

        // pipeline prologue: stages 0 and 1
        unsigned long long e0 = 0ull, e1 = 0ull;
        float v0 = 0.0f, v1 = 0.0f;
        if (lane < cnt)      { e0 = lst[lane];      v0 = __ldg(&rho[(unsigned)e0]); }
        if (lane + 32 < cnt) { e1 = lst[lane + 32]; v1 = __ldg(&rho[(unsigned)e1]); }

        #pragma unroll 1
        for (int idx = lane; idx < cnt; idx += 32) {
            // prefetch stage 2 (branchless-harmless if OOR: rv=0 contributes 0)
            unsigned long long e2 = 0ull; float v2 = 0.0f;
            int pp = idx + 64;
            if (pp < cnt) { e2 = lst[pp]; v2 = __ldg(&rho[(unsigned)e2]); }

            // process (e0, v0)
            unsigned pk = (unsigned)(e0 >> 32);
            int i = (int)(pk >> 10), j = (int)((pk >> 5) & 31), k = (int)(pk & 31);
            float x = __fadd_rn(__fmul_rn((float)(i - RMAXI), A_F), -drx);
            float y = __fadd_rn(__fmul_rn((float)(j - RMAXI), A_F), -dry);
            float z = __fadd_rn(__fmul_rn((float)(k - RMAXI), A_F), -drz);

            float r2 = x * x + y * y + z * z;
            float rinv = rsqrtf(fmaxf(r2, 1e-24f));
            float R  = r2 * rinv;
            float b  = RO_F - R;
            float s  = b - SHIFT_C;

            float ux = x * rinv, uy = y * rinv, uz = z * rinv;
            float ux2 = ux * ux, uy2 = uy * uy, uz2 = uz * uz;

            unsigned long long Yp[8];
            Yp[0] = pack2(0.28209479177387814f,
                          0.4886025119029199f * uy);
            Yp[1] = pack2(0.4886025119029199f * uz,
                          0.4886025119029199f * ux);
            Yp[2] = pack2(0.5462742152960396f * (2.0f * ux * uy),
                          1.0925484305920792f * (uy * uz));
            Yp[3] = pack2(0.31539156525252005f * (3.0f * uz2 - 1.0f),
                          1.0925484305920792f * (ux * uz));
            Yp[4] = pack2(0.5462742152960396f * (ux2 - uy2),
                          0.5900435899266435f * uy * (3.0f * ux2 - uy2));
            Yp[5] = pack2(1.445305721320277f  * (2.0f * ux * uy * uz),
                          0.4570457994644658f * uy * (5.0f * uz2 - 1.0f));
            Yp[6] = pack2(0.3731763325901154f * uz * (5.0f * uz2 - 3.0f),
                          0.4570457994644658f * ux * (5.0f * uz2 - 1.0f));
            Yp[7] = pack2(1.445305721320277f  * (ux2 - uy2) * uz,
                          0.5900435899266435f * ux * (ux2 - 3.0f * uy2));

            float t0 = r2 * (b * b) * v0;            // phi_0 * rho (0 if padded)
            unsigned long long s2 = pack2(s, s);
            unsigned long long t2 = pack2(t0, t0);

            #pragma unroll
            for (int m = 0; m < NRAD; ++m) {
                #pragma unroll
                for (int p = 0; p < 8; ++p)
                    ffma2(acc2[m * 8 + p], t2, Yp[p]);
                if (m < NRAD - 1) t2 = mul2(t2, s2);
            }

            // rotate pipeline
            e0 = e1; v0 = v1; e1 = e2; v1 = v2;
        }
    }

    // ---------- block reduction: 4 chunks of 32 coeffs via shared transpose ----------
    __syncthreads();    // ordering: all slist reads done before reusing smem bandwidth
    #pragma unroll 1
    for (int ch = 0; ch < 4; ++ch) {
        #pragma unroll
        for (int p = 0; p < 16; ++p) {
            float a, bb; unpack2(acc2[ch * 16 + p], a, bb);
            sred[tid][2 * p]     = a;
            sred[tid][2 * p + 1] = bb;
        }
        __syncthreads();
        {
            int q   = tid & 31;
            int seg = tid >> 5;
            float v = 0.0f;
            #pragma unroll
            for (int t = 0; t < 32; ++t) v += sred[seg * 32 + t][q];
            g_part[(((atom * NSPLIT + split) * NWARP) + seg) * NACC + ch * 32 + q] = v;
        }
        __syncthreads();
    }

    // ---------- last-block-per-atom finalization (fp64, W * binomial-shift) ----------
    __threadfence();
    if (tid == 0) s_old = atomicAdd(&g_cnt[atom], 1);
    __syncthreads();
    if (s_old == NSPLIT - 1) {
        __threadfence();
        const int lm = tid & 15;
        const int n  = tid >> 4;

        double vk[NRAD];
        #pragma unroll
        for (int k = 0; k < NRAD; ++k) {
            double a = 0.0;
            for (int pp = 0; pp < NSPLIT * NWARP; ++pp)
                a += (double)g_part[(atom * NSPLIT * NWARP + pp) * NACC + k * NANG + lm];
            vk[k] = a;
        }

        const double binom[NRAD][NRAD] = {
            {1,0,0,0,0,0,0,0},{1,1,0,0,0,0,0,0},{1,2,1,0,0,0,0,0},{1,3,3,1,0,0,0,0},
            {1,4,6,4,1,0,0,0},{1,5,10,10,5,1,0,0},{1,6,15,20,15,6,1,0},{1,7,21,35,35,21,7,1}};
        double cp[NRAD];
        cp[0] = 1.0;
        #pragma unroll
        for (int k = 1; k < NRAD; ++k) cp[k] = cp[k - 1] * (double)SHIFT_C;

        double mu[NRAD];
        #pragma unroll
        for (int m = 0; m < NRAD; ++m) {
            double a = 0.0;
            #pragma unroll
            for (int k = 0; k <= m; ++k) a += binom[m][k] * cp[m - k] * vk[k];
            mu[m] = a;
        }

        const double vcell = (36.0 / 180.0) * (36.0 / 180.0) * (36.0 / 180.0);
        double sacc = 0.0;
        #pragma unroll
        for (int m = 0; m < NRAD; ++m)
            sacc += (double)W[n * NRAD + m] * mu[m];
        out[atom * NACC + n * NANG + lm] = (float)(sacc * vcell);

        if (tid == 0) g_cnt[atom] = 0;       // reset for graph replay
    }
}

extern "C" void kernel_launch(void* const* d_in, const int* in_sizes, int n_in,
                              void* d_out, int out_size)
{
    const float* rho = (const float*)d_in[0];   // [180,180,180]
    const float* pos = (const float*)d_in[1];   // [64,3]
    const float* W   = (const float*)d_in[2];   // [8,8]
    float* out = (float*)d_out;                 // [64,128]

    dim3 grid(NSPLIT, NATOMS);                  // 4 x 64 = 256 blocks
    proj_kernel<<<grid, NTH>>>(rho, pos, W, out);
}